// round 9
// baseline (speedup 1.0000x reference)
#include <cuda_runtime.h>

#define N_TOK   131072
#define NEXP    8
#define NASSIGN 262144   // 2 * N_TOK

// ---------------- scratch (static __device__, no allocation) ----------------
__device__ float d_h1[(size_t)NASSIGN * 512];
__device__ float d_h2[(size_t)NASSIGN * 512];
__device__ float d_y [(size_t)NASSIGN * 256];
__device__ int   d_perm[NASSIGN];     // assignment row -> token
__device__ int   d_rowexp[NASSIGN];   // assignment row -> expert
__device__ int   d_rowpos[NASSIGN];   // (token,k) -> assignment row
__device__ float d_tokw[NASSIGN];     // (token,k) -> combine weight
__device__ unsigned char d_e0[N_TOK];
__device__ unsigned char d_e1[N_TOK];
__device__ int d_counts[NEXP];
__device__ int d_offsets[NEXP + 1];
__device__ int d_cursor[NEXP];

// ---------------- helpers ----------------
__device__ __forceinline__ void fma2(unsigned long long& d, unsigned long long a,
                                     unsigned long long b) {
    asm("fma.rn.f32x2 %0, %1, %2, %0;" : "+l"(d) : "l"(a), "l"(b));
}
__device__ __forceinline__ unsigned long long dup2(float x) {
    unsigned long long d;
    unsigned int u = __float_as_uint(x);
    asm("mov.b64 %0, {%1, %2};" : "=l"(d) : "r"(u), "r"(u));
    return d;
}
__device__ __forceinline__ float gelu_f(float v) {
    return 0.5f * v * (1.0f + erff(v * 0.70710678118654752440f));
}

// ---------------- 0) zero counters ----------------
__global__ void k_init() {
    if (threadIdx.x < NEXP) d_counts[threadIdx.x] = 0;
}

// ---------------- 1) gating: one warp per token ----------------
__global__ void k_gate(const float* __restrict__ x, const float* __restrict__ gw1,
                       const float* __restrict__ gw2) {
    __shared__ float sw1[16 * 256];   // transposed [j][i]
    __shared__ float sw2[16 * 8];     // [j][e]
    int tid = threadIdx.x;
    for (int p = tid; p < 16 * 256; p += 256) {
        int i = p >> 4, j = p & 15;
        sw1[j * 256 + i] = gw1[p];
    }
    if (tid < 128) sw2[tid] = gw2[tid];
    __syncthreads();

    int lane = tid & 31;
    int t = blockIdx.x * 8 + (tid >> 5);
    const float* xr = x + (size_t)t * 256;
    float xv[8];
#pragma unroll
    for (int m = 0; m < 8; m++) xv[m] = xr[lane + 32 * m];

    float acc[16];
#pragma unroll
    for (int j = 0; j < 16; j++) {
        float a = 0.f;
#pragma unroll
        for (int m = 0; m < 8; m++) a = fmaf(xv[m], sw1[j * 256 + lane + 32 * m], a);
        acc[j] = a;
    }
#pragma unroll
    for (int off = 16; off > 0; off >>= 1)
#pragma unroll
        for (int j = 0; j < 16; j++)
            acc[j] += __shfl_xor_sync(0xffffffffu, acc[j], off);

    float u[16];
#pragma unroll
    for (int j = 0; j < 16; j++) u[j] = tanhf(acc[j]);

    float lg[8];
#pragma unroll
    for (int e = 0; e < 8; e++) {
        float a = 0.f;
#pragma unroll
        for (int j = 0; j < 16; j++) a = fmaf(u[j], sw2[j * 8 + e], a);
        lg[e] = a;
    }
    float mx = lg[0];
#pragma unroll
    for (int e = 1; e < 8; e++) mx = fmaxf(mx, lg[e]);
    float p[8], s = 0.f;
#pragma unroll
    for (int e = 0; e < 8; e++) { p[e] = expf(lg[e] - mx); s += p[e]; }
#pragma unroll
    for (int e = 0; e < 8; e++) p[e] = p[e] / s;

    // top-2, earliest-index tie break (matches lax.top_k)
    int i0 = 0; float v0 = p[0];
#pragma unroll
    for (int e = 1; e < 8; e++) if (p[e] > v0) { v0 = p[e]; i0 = e; }
    int i1 = -1; float v1 = -1e30f;
#pragma unroll
    for (int e = 0; e < 8; e++) if (e != i0 && p[e] > v1) { v1 = p[e]; i1 = e; }
    float den = v0 + v1 + 1e-12f;
    v0 /= den; v1 /= den;

    if (lane == 0) {
        d_e0[t] = (unsigned char)i0;
        d_e1[t] = (unsigned char)i1;
        d_tokw[2 * t]     = v0;
        d_tokw[2 * t + 1] = v1;
        atomicAdd(&d_counts[i0], 1);
        atomicAdd(&d_counts[i1], 1);
    }
}

// ---------------- 2) scan ----------------
__global__ void k_scan() {
    if (threadIdx.x == 0) {
        int s = 0;
        for (int e = 0; e < NEXP; e++) {
            d_offsets[e] = s; d_cursor[e] = s; s += d_counts[e];
        }
        d_offsets[NEXP] = s;
    }
}

// ---------------- 3) scatter ----------------
__global__ void k_scatter() {
    int t = blockIdx.x * blockDim.x + threadIdx.x;
    int e0 = d_e0[t], e1 = d_e1[t];
    int r0 = atomicAdd(&d_cursor[e0], 1);
    int r1 = atomicAdd(&d_cursor[e1], 1);
    d_perm[r0] = t; d_rowexp[r0] = e0; d_rowpos[2 * t] = r0;
    d_perm[r1] = t; d_rowexp[r1] = e1; d_rowpos[2 * t + 1] = r1;
}

// ---------------- segment GEMM: C[rows of expert e] = A @ W[e] + b[e] ----------
// 128x128 CTA tile, BK=16, 256 threads, 8x8 microtile via fma.rn.f32x2.
template <int KDIM, int NDIM, bool GATHER>
__global__ void __launch_bounds__(256)
k_gemm(const float* __restrict__ A, const float* __restrict__ W,
       const float* __restrict__ bias, float* __restrict__ C) {
    __shared__ __align__(16) float As[2][16 * 128];
    __shared__ __align__(16) float Bs[2][16 * 128];
    const int e = blockIdx.z;
    const int seg1 = d_offsets[e + 1];
    const int m0 = d_offsets[e] + blockIdx.x * 128;
    if (m0 >= seg1) return;
    const int n0 = blockIdx.y * 128;
    const float* Bp = W + (size_t)e * KDIM * NDIM + n0;
    const float* biasp = bias + e * NDIM + n0;
    const int tid = threadIdx.x;
    const int a_m = tid >> 2;           // 0..63
    const int a_k = (tid & 3) << 2;     // 0,4,8,12
    const int b_k = tid >> 5;           // 0..7
    const int b_n = (tid & 31) << 2;    // 0..124

    const float* arow0 = nullptr;
    const float* arow1 = nullptr;
    {
        int r0 = m0 + a_m, r1 = r0 + 64;
        if (r0 < seg1) arow0 = A + (GATHER ? (size_t)d_perm[r0] * KDIM : (size_t)r0 * KDIM);
        if (r1 < seg1) arow1 = A + (GATHER ? (size_t)d_perm[r1] * KDIM : (size_t)r1 * KDIM);
    }

    const float4 z4 = make_float4(0.f, 0.f, 0.f, 0.f);
    float4 ra0, ra1, rb0, rb1;
    ra0 = arow0 ? *(const float4*)(arow0 + a_k) : z4;
    ra1 = arow1 ? *(const float4*)(arow1 + a_k) : z4;
    rb0 = *(const float4*)(Bp + (size_t)b_k * NDIM + b_n);
    rb1 = *(const float4*)(Bp + (size_t)(b_k + 8) * NDIM + b_n);
    {
        float* as = As[0]; float* bs = Bs[0];
        as[(a_k + 0) * 128 + a_m] = ra0.x; as[(a_k + 1) * 128 + a_m] = ra0.y;
        as[(a_k + 2) * 128 + a_m] = ra0.z; as[(a_k + 3) * 128 + a_m] = ra0.w;
        as[(a_k + 0) * 128 + a_m + 64] = ra1.x; as[(a_k + 1) * 128 + a_m + 64] = ra1.y;
        as[(a_k + 2) * 128 + a_m + 64] = ra1.z; as[(a_k + 3) * 128 + a_m + 64] = ra1.w;
        *(float4*)&bs[b_k * 128 + b_n] = rb0;
        *(float4*)&bs[(b_k + 8) * 128 + b_n] = rb1;
    }
    __syncthreads();

    unsigned long long acc[8][4];
#pragma unroll
    for (int i = 0; i < 8; i++)
#pragma unroll
        for (int j = 0; j < 4; j++) acc[i][j] = 0ULL;

    const int tx = (tid & 15) << 3;   // col 0..120
    const int ty = (tid >> 4) << 3;   // row 0..120
    constexpr int NT = KDIM / 16;

#pragma unroll 1
    for (int kt = 0; kt < NT; kt++) {
        const int buf = kt & 1;
        if (kt + 1 < NT) {
            const int kk = (kt + 1) * 16;
            ra0 = arow0 ? *(const float4*)(arow0 + kk + a_k) : z4;
            ra1 = arow1 ? *(const float4*)(arow1 + kk + a_k) : z4;
            rb0 = *(const float4*)(Bp + (size_t)(kk + b_k) * NDIM + b_n);
            rb1 = *(const float4*)(Bp + (size_t)(kk + b_k + 8) * NDIM + b_n);
        }
        const float* as = As[buf];
        const float* bs = Bs[buf];
#pragma unroll
        for (int k = 0; k < 16; k++) {
            union { float4 f; unsigned long long u[2]; } b0, b1;
            b0.f = *(const float4*)&bs[k * 128 + tx];
            b1.f = *(const float4*)&bs[k * 128 + tx + 4];
            float4 a0 = *(const float4*)&as[k * 128 + ty];
            float4 a1 = *(const float4*)&as[k * 128 + ty + 4];
            float av[8] = {a0.x, a0.y, a0.z, a0.w, a1.x, a1.y, a1.z, a1.w};
#pragma unroll
            for (int i = 0; i < 8; i++) {
                unsigned long long ad = dup2(av[i]);
                fma2(acc[i][0], ad, b0.u[0]);
                fma2(acc[i][1], ad, b0.u[1]);
                fma2(acc[i][2], ad, b1.u[0]);
                fma2(acc[i][3], ad, b1.u[1]);
            }
        }
        if (kt + 1 < NT) {
            float* was = As[buf ^ 1]; float* wbs = Bs[buf ^ 1];
            was[(a_k + 0) * 128 + a_m] = ra0.x; was[(a_k + 1) * 128 + a_m] = ra0.y;
            was[(a_k + 2) * 128 + a_m] = ra0.z; was[(a_k + 3) * 128 + a_m] = ra0.w;
            was[(a_k + 0) * 128 + a_m + 64] = ra1.x; was[(a_k + 1) * 128 + a_m + 64] = ra1.y;
            was[(a_k + 2) * 128 + a_m + 64] = ra1.z; was[(a_k + 3) * 128 + a_m + 64] = ra1.w;
            *(float4*)&wbs[b_k * 128 + b_n] = rb0;
            *(float4*)&wbs[(b_k + 8) * 128 + b_n] = rb1;
        }
        __syncthreads();
    }

    float4 bv0 = *(const float4*)(biasp + tx);
    float4 bv1 = *(const float4*)(biasp + tx + 4);
#pragma unroll
    for (int i = 0; i < 8; i++) {
        int row = m0 + ty + i;
        if (row >= seg1) break;
        union { float4 f; unsigned long long u[2]; } c0, c1;
        c0.u[0] = acc[i][0]; c0.u[1] = acc[i][1];
        c1.u[0] = acc[i][2]; c1.u[1] = acc[i][3];
        c0.f.x += bv0.x; c0.f.y += bv0.y; c0.f.z += bv0.z; c0.f.w += bv0.w;
        c1.f.x += bv1.x; c1.f.y += bv1.y; c1.f.z += bv1.z; c1.f.w += bv1.w;
        float* cp = C + (size_t)row * NDIM + n0;
        *(float4*)(cp + tx) = c0.f;
        *(float4*)(cp + tx + 4) = c1.f;
    }
}

// ---------------- LayerNorm + exact GELU (in-place), warp per 512-row --------
__global__ void k_ln_gelu(float* __restrict__ h, const float* __restrict__ g,
                          const float* __restrict__ be) {
    int lane = threadIdx.x & 31;
    int r = blockIdx.x * 8 + (threadIdx.x >> 5);
    float* hr = h + (size_t)r * 512;
    float4 v[4];
    float s = 0.f;
#pragma unroll
    for (int i = 0; i < 4; i++) {
        v[i] = *(const float4*)(hr + i * 128 + lane * 4);
        s += v[i].x + v[i].y + v[i].z + v[i].w;
    }
#pragma unroll
    for (int off = 16; off > 0; off >>= 1) s += __shfl_xor_sync(0xffffffffu, s, off);
    float mu = s * (1.f / 512.f);
    float sq = 0.f;
#pragma unroll
    for (int i = 0; i < 4; i++) {
        float dx = v[i].x - mu, dy = v[i].y - mu, dz = v[i].z - mu, dw = v[i].w - mu;
        sq += dx * dx + dy * dy + dz * dz + dw * dw;
    }
#pragma unroll
    for (int off = 16; off > 0; off >>= 1) sq += __shfl_xor_sync(0xffffffffu, sq, off);
    float rs = rsqrtf(sq * (1.f / 512.f) + 1e-5f);
    int e = d_rowexp[r];
    const float* gp = g + e * 512;
    const float* bp = be + e * 512;
#pragma unroll
    for (int i = 0; i < 4; i++) {
        float4 gv = *(const float4*)(gp + i * 128 + lane * 4);
        float4 bv = *(const float4*)(bp + i * 128 + lane * 4);
        float4 o;
        o.x = gelu_f(fmaf((v[i].x - mu) * rs, gv.x, bv.x));
        o.y = gelu_f(fmaf((v[i].y - mu) * rs, gv.y, bv.y));
        o.z = gelu_f(fmaf((v[i].z - mu) * rs, gv.z, bv.z));
        o.w = gelu_f(fmaf((v[i].w - mu) * rs, gv.w, bv.w));
        *(float4*)(hr + i * 128 + lane * 4) = o;
    }
}

// ---------------- combine ----------------
__global__ void k_combine(float* __restrict__ out) {
    int t = blockIdx.x;
    int c = threadIdx.x;   // 64 float4 lanes
    int r0 = d_rowpos[2 * t], r1 = d_rowpos[2 * t + 1];
    float w0 = d_tokw[2 * t], w1 = d_tokw[2 * t + 1];
    float4 a = *(const float4*)(d_y + (size_t)r0 * 256 + c * 4);
    float4 b = *(const float4*)(d_y + (size_t)r1 * 256 + c * 4);
    float4 o;
    o.x = fmaf(w0, a.x, w1 * b.x);
    o.y = fmaf(w0, a.y, w1 * b.y);
    o.z = fmaf(w0, a.z, w1 * b.z);
    o.w = fmaf(w0, a.w, w1 * b.w);
    *(float4*)(out + (size_t)t * 256 + c * 4) = o;
}

// ---------------- launcher ----------------
extern "C" void kernel_launch(void* const* d_in, const int* in_sizes, int n_in,
                              void* d_out, int out_size) {
    (void)in_sizes; (void)n_in; (void)out_size;
    const float* x   = (const float*)d_in[0];
    const float* gw1 = (const float*)d_in[1];
    const float* gw2 = (const float*)d_in[2];
    const float* W1  = (const float*)d_in[3];
    const float* b1  = (const float*)d_in[4];
    const float* g1  = (const float*)d_in[5];
    const float* be1 = (const float*)d_in[6];
    const float* W2  = (const float*)d_in[7];
    const float* b2  = (const float*)d_in[8];
    const float* g2  = (const float*)d_in[9];
    const float* be2 = (const float*)d_in[10];
    const float* W3  = (const float*)d_in[11];
    const float* b3  = (const float*)d_in[12];
    float* out = (float*)d_out;

    void *p_h1 = nullptr, *p_h2 = nullptr, *p_y = nullptr;
    cudaGetSymbolAddress(&p_h1, d_h1);
    cudaGetSymbolAddress(&p_h2, d_h2);
    cudaGetSymbolAddress(&p_y,  d_y);
    float* h1 = (float*)p_h1;
    float* h2 = (float*)p_h2;
    float* y  = (float*)p_y;

    k_init<<<1, 32>>>();
    k_gate<<<N_TOK / 8, 256>>>(x, gw1, gw2);
    k_scan<<<1, 32>>>();
    k_scatter<<<N_TOK / 256, 256>>>();

    // GEMM1: h1 = gather(x) @ W1 + b1   [rows x 256] @ [256 x 512]
    dim3 gA(1024, 4, 8);
    k_gemm<256, 512, true><<<gA, 256>>>(x, W1, b1, h1);
    k_ln_gelu<<<NASSIGN / 8, 256>>>(h1, g1, be1);

    // GEMM2: h2 = h1 @ W2 + b2   [rows x 512] @ [512 x 512]
    k_gemm<512, 512, false><<<gA, 256>>>(h1, W2, b2, h2);
    k_ln_gelu<<<NASSIGN / 8, 256>>>(h2, g2, be2);

    // GEMM3: y = h2 @ W3 + b3   [rows x 512] @ [512 x 256]
    dim3 gC(1024, 2, 8);
    k_gemm<512, 256, false><<<gC, 256>>>(h2, W3, b3, y);

    k_combine<<<N_TOK, 64>>>(out);
}

// round 12
// speedup vs baseline: 1.0009x; 1.0009x over previous
#include <cuda_runtime.h>

#define N_TOK   131072
#define NEXP    8
#define NASSIGN 262144   // 2 * N_TOK

// ---------------- scratch (static __device__, no allocation) ----------------
__device__ float d_h1[(size_t)NASSIGN * 512];
__device__ float d_h2[(size_t)NASSIGN * 512];
__device__ float d_y [(size_t)NASSIGN * 256];
__device__ int   d_perm[NASSIGN];     // assignment row -> token
__device__ int   d_rowexp[NASSIGN];   // assignment row -> expert
__device__ int   d_rowpos[NASSIGN];   // (token,k) -> assignment row
__device__ float d_tokw[NASSIGN];     // (token,k) -> combine weight
__device__ unsigned char d_e0[N_TOK];
__device__ unsigned char d_e1[N_TOK];
__device__ int d_counts[NEXP];
__device__ int d_offsets[NEXP + 1];
__device__ int d_cursor[NEXP];

// ---------------- helpers ----------------
__device__ __forceinline__ void fma2(unsigned long long& d, unsigned long long a,
                                     unsigned long long b) {
    asm("fma.rn.f32x2 %0, %1, %2, %0;" : "+l"(d) : "l"(a), "l"(b));
}
__device__ __forceinline__ unsigned long long dup2(float x) {
    unsigned long long d;
    unsigned int u = __float_as_uint(x);
    asm("mov.b64 %0, {%1, %2};" : "=l"(d) : "r"(u), "r"(u));
    return d;
}
__device__ __forceinline__ float gelu_f(float v) {
    return 0.5f * v * (1.0f + erff(v * 0.70710678118654752440f));
}

// ---------------- 0) zero counters ----------------
__global__ void k_init() {
    if (threadIdx.x < NEXP) d_counts[threadIdx.x] = 0;
}

// ---------------- 1) gating: one warp per token ----------------
__global__ void k_gate(const float* __restrict__ x, const float* __restrict__ gw1,
                       const float* __restrict__ gw2) {
    __shared__ float sw1[16 * 256];   // transposed [j][i]
    __shared__ float sw2[16 * 8];     // [j][e]
    int tid = threadIdx.x;
    for (int p = tid; p < 16 * 256; p += 256) {
        int i = p >> 4, j = p & 15;
        sw1[j * 256 + i] = gw1[p];
    }
    if (tid < 128) sw2[tid] = gw2[tid];
    __syncthreads();

    int lane = tid & 31;
    int t = blockIdx.x * 8 + (tid >> 5);
    const float* xr = x + (size_t)t * 256;
    float xv[8];
#pragma unroll
    for (int m = 0; m < 8; m++) xv[m] = xr[lane + 32 * m];

    float acc[16];
#pragma unroll
    for (int j = 0; j < 16; j++) {
        float a = 0.f;
#pragma unroll
        for (int m = 0; m < 8; m++) a = fmaf(xv[m], sw1[j * 256 + lane + 32 * m], a);
        acc[j] = a;
    }
#pragma unroll
    for (int off = 16; off > 0; off >>= 1)
#pragma unroll
        for (int j = 0; j < 16; j++)
            acc[j] += __shfl_xor_sync(0xffffffffu, acc[j], off);

    float u[16];
#pragma unroll
    for (int j = 0; j < 16; j++) u[j] = tanhf(acc[j]);

    float lg[8];
#pragma unroll
    for (int e = 0; e < 8; e++) {
        float a = 0.f;
#pragma unroll
        for (int j = 0; j < 16; j++) a = fmaf(u[j], sw2[j * 8 + e], a);
        lg[e] = a;
    }
    float mx = lg[0];
#pragma unroll
    for (int e = 1; e < 8; e++) mx = fmaxf(mx, lg[e]);
    float p[8], s = 0.f;
#pragma unroll
    for (int e = 0; e < 8; e++) { p[e] = expf(lg[e] - mx); s += p[e]; }
#pragma unroll
    for (int e = 0; e < 8; e++) p[e] = p[e] / s;

    // top-2, earliest-index tie break (matches lax.top_k)
    int i0 = 0; float v0 = p[0];
#pragma unroll
    for (int e = 1; e < 8; e++) if (p[e] > v0) { v0 = p[e]; i0 = e; }
    int i1 = -1; float v1 = -1e30f;
#pragma unroll
    for (int e = 0; e < 8; e++) if (e != i0 && p[e] > v1) { v1 = p[e]; i1 = e; }
    float den = v0 + v1 + 1e-12f;
    v0 /= den; v1 /= den;

    if (lane == 0) {
        d_e0[t] = (unsigned char)i0;
        d_e1[t] = (unsigned char)i1;
        d_tokw[2 * t]     = v0;
        d_tokw[2 * t + 1] = v1;
        atomicAdd(&d_counts[i0], 1);
        atomicAdd(&d_counts[i1], 1);
    }
}

// ---------------- 2) scan ----------------
__global__ void k_scan() {
    if (threadIdx.x == 0) {
        int s = 0;
        for (int e = 0; e < NEXP; e++) {
            d_offsets[e] = s; d_cursor[e] = s; s += d_counts[e];
        }
        d_offsets[NEXP] = s;
    }
}

// ---------------- 3) scatter ----------------
__global__ void k_scatter() {
    int t = blockIdx.x * blockDim.x + threadIdx.x;
    int e0 = d_e0[t], e1 = d_e1[t];
    int r0 = atomicAdd(&d_cursor[e0], 1);
    int r1 = atomicAdd(&d_cursor[e1], 1);
    d_perm[r0] = t; d_rowexp[r0] = e0; d_rowpos[2 * t] = r0;
    d_perm[r1] = t; d_rowexp[r1] = e1; d_rowpos[2 * t + 1] = r1;
}

// ---------------- segment GEMM: C[rows of expert e] = A @ W[e] + b[e] ----------
// 128x128 CTA tile, BK=16, 256 threads, 8x8 microtile via fma.rn.f32x2.
template <int KDIM, int NDIM, bool GATHER>
__global__ void __launch_bounds__(256)
k_gemm(const float* __restrict__ A, const float* __restrict__ W,
       const float* __restrict__ bias, float* __restrict__ C) {
    __shared__ __align__(16) float As[2][16 * 128];
    __shared__ __align__(16) float Bs[2][16 * 128];
    const int e = blockIdx.z;
    const int seg1 = d_offsets[e + 1];
    const int m0 = d_offsets[e] + blockIdx.x * 128;
    if (m0 >= seg1) return;
    const int n0 = blockIdx.y * 128;
    const float* Bp = W + (size_t)e * KDIM * NDIM + n0;
    const float* biasp = bias + e * NDIM + n0;
    const int tid = threadIdx.x;
    const int a_m = tid >> 2;           // 0..63
    const int a_k = (tid & 3) << 2;     // 0,4,8,12
    const int b_k = tid >> 5;           // 0..7
    const int b_n = (tid & 31) << 2;    // 0..124

    const float* arow0 = nullptr;
    const float* arow1 = nullptr;
    {
        int r0 = m0 + a_m, r1 = r0 + 64;
        if (r0 < seg1) arow0 = A + (GATHER ? (size_t)d_perm[r0] * KDIM : (size_t)r0 * KDIM);
        if (r1 < seg1) arow1 = A + (GATHER ? (size_t)d_perm[r1] * KDIM : (size_t)r1 * KDIM);
    }

    const float4 z4 = make_float4(0.f, 0.f, 0.f, 0.f);
    float4 ra0, ra1, rb0, rb1;
    ra0 = arow0 ? *(const float4*)(arow0 + a_k) : z4;
    ra1 = arow1 ? *(const float4*)(arow1 + a_k) : z4;
    rb0 = *(const float4*)(Bp + (size_t)b_k * NDIM + b_n);
    rb1 = *(const float4*)(Bp + (size_t)(b_k + 8) * NDIM + b_n);
    {
        float* as = As[0]; float* bs = Bs[0];
        as[(a_k + 0) * 128 + a_m] = ra0.x; as[(a_k + 1) * 128 + a_m] = ra0.y;
        as[(a_k + 2) * 128 + a_m] = ra0.z; as[(a_k + 3) * 128 + a_m] = ra0.w;
        as[(a_k + 0) * 128 + a_m + 64] = ra1.x; as[(a_k + 1) * 128 + a_m + 64] = ra1.y;
        as[(a_k + 2) * 128 + a_m + 64] = ra1.z; as[(a_k + 3) * 128 + a_m + 64] = ra1.w;
        *(float4*)&bs[b_k * 128 + b_n] = rb0;
        *(float4*)&bs[(b_k + 8) * 128 + b_n] = rb1;
    }
    __syncthreads();

    unsigned long long acc[8][4];
#pragma unroll
    for (int i = 0; i < 8; i++)
#pragma unroll
        for (int j = 0; j < 4; j++) acc[i][j] = 0ULL;

    const int tx = (tid & 15) << 3;   // col 0..120
    const int ty = (tid >> 4) << 3;   // row 0..120
    constexpr int NT = KDIM / 16;

#pragma unroll 1
    for (int kt = 0; kt < NT; kt++) {
        const int buf = kt & 1;
        if (kt + 1 < NT) {
            const int kk = (kt + 1) * 16;
            ra0 = arow0 ? *(const float4*)(arow0 + kk + a_k) : z4;
            ra1 = arow1 ? *(const float4*)(arow1 + kk + a_k) : z4;
            rb0 = *(const float4*)(Bp + (size_t)(kk + b_k) * NDIM + b_n);
            rb1 = *(const float4*)(Bp + (size_t)(kk + b_k + 8) * NDIM + b_n);
        }
        const float* as = As[buf];
        const float* bs = Bs[buf];
#pragma unroll
        for (int k = 0; k < 16; k++) {
            union { float4 f; unsigned long long u[2]; } b0, b1;
            b0.f = *(const float4*)&bs[k * 128 + tx];
            b1.f = *(const float4*)&bs[k * 128 + tx + 4];
            float4 a0 = *(const float4*)&as[k * 128 + ty];
            float4 a1 = *(const float4*)&as[k * 128 + ty + 4];
            float av[8] = {a0.x, a0.y, a0.z, a0.w, a1.x, a1.y, a1.z, a1.w};
#pragma unroll
            for (int i = 0; i < 8; i++) {
                unsigned long long ad = dup2(av[i]);
                fma2(acc[i][0], ad, b0.u[0]);
                fma2(acc[i][1], ad, b0.u[1]);
                fma2(acc[i][2], ad, b1.u[0]);
                fma2(acc[i][3], ad, b1.u[1]);
            }
        }
        if (kt + 1 < NT) {
            float* was = As[buf ^ 1]; float* wbs = Bs[buf ^ 1];
            was[(a_k + 0) * 128 + a_m] = ra0.x; was[(a_k + 1) * 128 + a_m] = ra0.y;
            was[(a_k + 2) * 128 + a_m] = ra0.z; was[(a_k + 3) * 128 + a_m] = ra0.w;
            was[(a_k + 0) * 128 + a_m + 64] = ra1.x; was[(a_k + 1) * 128 + a_m + 64] = ra1.y;
            was[(a_k + 2) * 128 + a_m + 64] = ra1.z; was[(a_k + 3) * 128 + a_m + 64] = ra1.w;
            *(float4*)&wbs[b_k * 128 + b_n] = rb0;
            *(float4*)&wbs[(b_k + 8) * 128 + b_n] = rb1;
        }
        __syncthreads();
    }

    float4 bv0 = *(const float4*)(biasp + tx);
    float4 bv1 = *(const float4*)(biasp + tx + 4);
#pragma unroll
    for (int i = 0; i < 8; i++) {
        int row = m0 + ty + i;
        if (row >= seg1) break;
        union { float4 f; unsigned long long u[2]; } c0, c1;
        c0.u[0] = acc[i][0]; c0.u[1] = acc[i][1];
        c1.u[0] = acc[i][2]; c1.u[1] = acc[i][3];
        c0.f.x += bv0.x; c0.f.y += bv0.y; c0.f.z += bv0.z; c0.f.w += bv0.w;
        c1.f.x += bv1.x; c1.f.y += bv1.y; c1.f.z += bv1.z; c1.f.w += bv1.w;
        float* cp = C + (size_t)row * NDIM + n0;
        *(float4*)(cp + tx) = c0.f;
        *(float4*)(cp + tx + 4) = c1.f;
    }
}

// ---------------- LayerNorm + exact GELU (in-place), warp per 512-row --------
__global__ void k_ln_gelu(float* __restrict__ h, const float* __restrict__ g,
                          const float* __restrict__ be) {
    int lane = threadIdx.x & 31;
    int r = blockIdx.x * 8 + (threadIdx.x >> 5);
    float* hr = h + (size_t)r * 512;
    float4 v[4];
    float s = 0.f;
#pragma unroll
    for (int i = 0; i < 4; i++) {
        v[i] = *(const float4*)(hr + i * 128 + lane * 4);
        s += v[i].x + v[i].y + v[i].z + v[i].w;
    }
#pragma unroll
    for (int off = 16; off > 0; off >>= 1) s += __shfl_xor_sync(0xffffffffu, s, off);
    float mu = s * (1.f / 512.f);
    float sq = 0.f;
#pragma unroll
    for (int i = 0; i < 4; i++) {
        float dx = v[i].x - mu, dy = v[i].y - mu, dz = v[i].z - mu, dw = v[i].w - mu;
        sq += dx * dx + dy * dy + dz * dz + dw * dw;
    }
#pragma unroll
    for (int off = 16; off > 0; off >>= 1) sq += __shfl_xor_sync(0xffffffffu, sq, off);
    float rs = rsqrtf(sq * (1.f / 512.f) + 1e-5f);
    int e = d_rowexp[r];
    const float* gp = g + e * 512;
    const float* bp = be + e * 512;
#pragma unroll
    for (int i = 0; i < 4; i++) {
        float4 gv = *(const float4*)(gp + i * 128 + lane * 4);
        float4 bv = *(const float4*)(bp + i * 128 + lane * 4);
        float4 o;
        o.x = gelu_f(fmaf((v[i].x - mu) * rs, gv.x, bv.x));
        o.y = gelu_f(fmaf((v[i].y - mu) * rs, gv.y, bv.y));
        o.z = gelu_f(fmaf((v[i].z - mu) * rs, gv.z, bv.z));
        o.w = gelu_f(fmaf((v[i].w - mu) * rs, gv.w, bv.w));
        *(float4*)(hr + i * 128 + lane * 4) = o;
    }
}

// ---------------- combine ----------------
__global__ void k_combine(float* __restrict__ out) {
    int t = blockIdx.x;
    int c = threadIdx.x;   // 64 float4 lanes
    int r0 = d_rowpos[2 * t], r1 = d_rowpos[2 * t + 1];
    float w0 = d_tokw[2 * t], w1 = d_tokw[2 * t + 1];
    float4 a = *(const float4*)(d_y + (size_t)r0 * 256 + c * 4);
    float4 b = *(const float4*)(d_y + (size_t)r1 * 256 + c * 4);
    float4 o;
    o.x = fmaf(w0, a.x, w1 * b.x);
    o.y = fmaf(w0, a.y, w1 * b.y);
    o.z = fmaf(w0, a.z, w1 * b.z);
    o.w = fmaf(w0, a.w, w1 * b.w);
    *(float4*)(out + (size_t)t * 256 + c * 4) = o;
}

// ---------------- launcher ----------------
extern "C" void kernel_launch(void* const* d_in, const int* in_sizes, int n_in,
                              void* d_out, int out_size) {
    (void)in_sizes; (void)n_in; (void)out_size;
    const float* x   = (const float*)d_in[0];
    const float* gw1 = (const float*)d_in[1];
    const float* gw2 = (const float*)d_in[2];
    const float* W1  = (const float*)d_in[3];
    const float* b1  = (const float*)d_in[4];
    const float* g1  = (const float*)d_in[5];
    const float* be1 = (const float*)d_in[6];
    const float* W2  = (const float*)d_in[7];
    const float* b2  = (const float*)d_in[8];
    const float* g2  = (const float*)d_in[9];
    const float* be2 = (const float*)d_in[10];
    const float* W3  = (const float*)d_in[11];
    const float* b3  = (const float*)d_in[12];
    float* out = (float*)d_out;

    void *p_h1 = nullptr, *p_h2 = nullptr, *p_y = nullptr;
    cudaGetSymbolAddress(&p_h1, d_h1);
    cudaGetSymbolAddress(&p_h2, d_h2);
    cudaGetSymbolAddress(&p_y,  d_y);
    float* h1 = (float*)p_h1;
    float* h2 = (float*)p_h2;
    float* y  = (float*)p_y;

    k_init<<<1, 32>>>();
    k_gate<<<N_TOK / 8, 256>>>(x, gw1, gw2);
    k_scan<<<1, 32>>>();
    k_scatter<<<N_TOK / 256, 256>>>();

    // GEMM1: h1 = gather(x) @ W1 + b1   [rows x 256] @ [256 x 512]
    dim3 gA(1024, 4, 8);
    k_gemm<256, 512, true><<<gA, 256>>>(x, W1, b1, h1);
    k_ln_gelu<<<NASSIGN / 8, 256>>>(h1, g1, be1);

    // GEMM2: h2 = h1 @ W2 + b2   [rows x 512] @ [512 x 512]
    k_gemm<512, 512, false><<<gA, 256>>>(h1, W2, b2, h2);
    k_ln_gelu<<<NASSIGN / 8, 256>>>(h2, g2, be2);

    // GEMM3: y = h2 @ W3 + b3   [rows x 512] @ [512 x 256]
    dim3 gC(1024, 2, 8);
    k_gemm<512, 256, false><<<gC, 256>>>(h2, W3, b3, y);

    k_combine<<<N_TOK, 64>>>(out);
}